// round 11
// baseline (speedup 1.0000x reference)
#include <cuda_runtime.h>
#include <cuda_bf16.h>
#include <cuda_fp16.h>
#include <cstdint>
#include <cstddef>

#define BB   4
#define CC   256
#define LL   4096
#define C8   32
#define OTOT 320   // 32 q + 32 k + 256 v rows

// ---------------- scratch (device globals; no allocation allowed) ----------
__device__ __align__(256) float g_W[OTOT * CC];                 // packed [Wq;Wk;Wv]
__device__ float g_bias[OTOT];
__device__ __align__(256) __nv_bfloat16 g_vh[(size_t)BB * CC * LL];   // v in bf16
__device__ __align__(256) __half g_qT[(size_t)BB * LL * C8];          // q transposed fp16 [b][i][c]
__device__ __align__(256) __half g_kT[(size_t)BB * LL * C8];          // k transposed fp16 [b][j][c]
__device__ __align__(256) __nv_bfloat16 g_Eh[(size_t)BB * LL * LL];   // exp(S) bf16 (128 MB)
__device__ float g_rowsum[BB * LL];

// ---------------- PTX helpers (sm_80-era only: family-target safe) ----------
__device__ __forceinline__ uint32_t smem_u32(const void* p) {
    uint32_t a;
    asm("{ .reg .u64 t; cvta.to.shared.u64 t, %1; cvt.u32.u64 %0, t; }" : "=r"(a) : "l"(p));
    return a;
}
__device__ __forceinline__ void cp_async16(uint32_t dst, const void* src) {
    asm volatile("cp.async.cg.shared.global [%0], [%1], 16;" :: "r"(dst), "l"(src));
}
#define CP_COMMIT() asm volatile("cp.async.commit_group;" ::: "memory")
#define CP_WAIT(n)  asm volatile("cp.async.wait_group %0;" :: "n"(n) : "memory")

__device__ __forceinline__ void ldsm4(uint32_t* r, uint32_t addr) {
    asm volatile("ldmatrix.sync.aligned.m8n8.x4.shared.b16 {%0,%1,%2,%3}, [%4];"
                 : "=r"(r[0]), "=r"(r[1]), "=r"(r[2]), "=r"(r[3]) : "r"(addr));
}
__device__ __forceinline__ void mma16816_bf16(float* d, const uint32_t* a, const uint32_t* b) {
    asm volatile(
        "mma.sync.aligned.m16n8k16.row.col.f32.bf16.bf16.f32 "
        "{%0,%1,%2,%3}, {%4,%5,%6,%7}, {%8,%9}, {%0,%1,%2,%3};"
        : "+f"(d[0]), "+f"(d[1]), "+f"(d[2]), "+f"(d[3])
        : "r"(a[0]), "r"(a[1]), "r"(a[2]), "r"(a[3]), "r"(b[0]), "r"(b[1]));
}
__device__ __forceinline__ void mma16816_f16(float* d, const uint32_t* a, const uint32_t* b) {
    asm volatile(
        "mma.sync.aligned.m16n8k16.row.col.f32.f16.f16.f32 "
        "{%0,%1,%2,%3}, {%4,%5,%6,%7}, {%8,%9}, {%0,%1,%2,%3};"
        : "+f"(d[0]), "+f"(d[1]), "+f"(d[2]), "+f"(d[3])
        : "r"(a[0]), "r"(a[1]), "r"(a[2]), "r"(a[3]), "r"(b[0]), "r"(b[1]));
}

// SW64 swizzle for 64-byte rows.
__device__ __forceinline__ uint32_t sw64(uint32_t off) {
    return off ^ ((off >> 3) & 0x30);
}

// ---------------- kernel 0: pack weights + biases ---------------------------
__global__ void pack_kernel(const float* __restrict__ Wq, const float* __restrict__ bq,
                            const float* __restrict__ Wk, const float* __restrict__ bk,
                            const float* __restrict__ Wv, const float* __restrict__ bv) {
    int tid = blockIdx.x * blockDim.x + threadIdx.x;
    int stride = gridDim.x * blockDim.x;
    for (int idx = tid; idx < OTOT * CC; idx += stride) {
        int o = idx / CC;
        int c = idx % CC;
        float w;
        if (o < 32)       w = Wq[o * CC + c];
        else if (o < 64)  w = Wk[(o - 32) * CC + c];
        else              w = Wv[(o - 64) * CC + c];
        g_W[idx] = w;
    }
    if (tid < OTOT) {
        g_bias[tid] = (tid < 32) ? bq[tid] : (tid < 64) ? bk[tid - 32] : bv[tid - 64];
    }
}

// ---------------- kernel 1: qkv = W[320,256] @ x[b,256,4096] + bias ---------
// 64x64x16 SGEMM; v emitted as bf16 (g_vh), q/k emitted transposed fp16.
__global__ __launch_bounds__(256) void qkv_kernel(const float* __restrict__ x) {
    const int b  = blockIdx.z;
    const int m0 = blockIdx.y * 64;
    const int n0 = blockIdx.x * 64;

    __shared__ float As[16][68];
    __shared__ float Bs[16][64];

    const int t  = threadIdx.x;
    const int tx = t % 16, ty = t / 16;

    float acc[4][4];
#pragma unroll
    for (int i = 0; i < 4; i++)
#pragma unroll
        for (int j = 0; j < 4; j++) acc[i][j] = 0.f;

    for (int k0 = 0; k0 < CC; k0 += 16) {
        {
            int c = t % 16;
            int mbase = t / 16;
#pragma unroll
            for (int s = 0; s < 4; s++) {
                int m = mbase + 16 * s;
                As[c][m] = g_W[(m0 + m) * CC + k0 + c];
            }
        }
        {
            int n = t % 64;
            int kb = t / 64;
#pragma unroll
            for (int s = 0; s < 4; s++) {
                int kk = kb + 4 * s;
                Bs[kk][n] = x[((size_t)b * CC + k0 + kk) * LL + n0 + n];
            }
        }
        __syncthreads();
#pragma unroll
        for (int kk = 0; kk < 16; kk++) {
            float4 a  = *(const float4*)&As[kk][ty * 4];
            float4 b4 = *(const float4*)&Bs[kk][tx * 4];
            float av[4] = {a.x, a.y, a.z, a.w};
            float bv4[4] = {b4.x, b4.y, b4.z, b4.w};
#pragma unroll
            for (int i = 0; i < 4; i++)
#pragma unroll
                for (int j = 0; j < 4; j++) acc[i][j] += av[i] * bv4[j];
        }
        __syncthreads();
    }

#pragma unroll
    for (int i = 0; i < 4; i++) {
        int o = m0 + ty * 4 + i;
        float bias = g_bias[o];
        float rv[4];
#pragma unroll
        for (int j = 0; j < 4; j++) rv[j] = acc[i][j] + bias;

        if (o >= 64) {
            // v: bf16 row-major
            __nv_bfloat162 h0 = __floats2bfloat162_rn(rv[0], rv[1]);
            __nv_bfloat162 h1 = __floats2bfloat162_rn(rv[2], rv[3]);
            uint2 pk;
            pk.x = *(uint32_t*)&h0;
            pk.y = *(uint32_t*)&h1;
            *(uint2*)&g_vh[((size_t)b * CC + (o - 64)) * LL + n0 + tx * 4] = pk;
        } else if (o < 32) {
            // q: fp16 transposed [l][c]
#pragma unroll
            for (int j = 0; j < 4; j++)
                g_qT[((size_t)b * LL + n0 + tx * 4 + j) * C8 + o] = __float2half(rv[j]);
        } else {
            // k: fp16 transposed [l][c]
#pragma unroll
            for (int j = 0; j < 4; j++)
                g_kT[((size_t)b * LL + n0 + tx * 4 + j) * C8 + (o - 32)] = __float2half(rv[j]);
        }
    }
}

// ---------------- kernel 2: E = exp(q^T k) via mma.sync fp16 ---------------
#define NJ   (LL / 128)      // 32
#define KTB  (128 * 64)      // 8192 bytes per k tile (128 rows x 32 fp16)

__global__ __launch_bounds__(256) void attn_mma_kernel() {
    __shared__ __align__(1024) uint8_t sQ[KTB];
    __shared__ __align__(1024) uint8_t sK[2][KTB];
    __shared__ float srs[4][128];

    const int b  = blockIdx.y;
    const int i0 = blockIdx.x * 128;

    const int t = threadIdx.x;
    const int w = t >> 5;
    const int l = t & 31;
    const int wm = w & 1;
    const int wn = w >> 1;

    const uint32_t sQa = smem_u32(sQ);
    const uint32_t sKa = smem_u32(sK);

    const int ldr = t >> 1;
    const int ldc = (t & 1) * 2;
    const uint32_t off0 = sw64((uint32_t)ldr * 64u + (uint32_t)ldc * 16u);
    const uint32_t off1 = sw64((uint32_t)ldr * 64u + (uint32_t)ldc * 16u + 16u);

    const __half* Qg = g_qT + ((size_t)b * LL + i0 + ldr) * C8 + ldc * 8;
    cp_async16(sQa + off0, Qg);
    cp_async16(sQa + off1, Qg + 8);
    CP_COMMIT();
    {
        const __half* Kg = g_kT + ((size_t)b * LL + ldr) * C8 + ldc * 8;
        cp_async16(sKa + off0, Kg);
        cp_async16(sKa + off1, Kg + 8);
        CP_COMMIT();
    }

    CP_WAIT(1);
    __syncthreads();

    const int arow = wm * 64 + (l & 15);
    const int ac16 = l >> 4;
    uint32_t afr[4][2][4];
#pragma unroll
    for (int im = 0; im < 4; im++)
#pragma unroll
        for (int ks = 0; ks < 2; ks++) {
            int row = arow + im * 16;
            int c16 = ks * 2 + ac16;
            uint32_t off = (uint32_t)row * 64u + (uint32_t)((c16 ^ ((row & 6) >> 1)) * 16);
            ldsm4(afr[im][ks], sQa + off);
        }

    const int brow = wn * 32 + (l & 7) + ((l >> 4) << 3);
    const int bc16 = (l >> 3) & 1;

    float rsum[8];
#pragma unroll
    for (int r = 0; r < 8; r++) rsum[r] = 0.f;

    __nv_bfloat16* Ebase = g_Eh + ((size_t)b * LL + i0) * LL;

    const int rl0 = wm * 64 + (l >> 2);
    const int cc0 = wn * 32 + 2 * (l & 3);

#pragma unroll 1
    for (int jt = 0; jt < NJ; jt++) {
        const int buf = jt & 1;

        if (jt + 1 < NJ) {
            const __half* Kg2 = g_kT + ((size_t)b * LL + (jt + 1) * 128 + ldr) * C8 + ldc * 8;
            uint32_t d = sKa + (buf ^ 1) * KTB;
            cp_async16(d + off0, Kg2);
            cp_async16(d + off1, Kg2 + 8);
            CP_COMMIT();
            CP_WAIT(1);
        } else {
            CP_WAIT(0);
        }
        __syncthreads();

        const uint32_t kb = sKa + buf * KTB;

        float acc[4][4][4];
#pragma unroll
        for (int i = 0; i < 4; i++)
#pragma unroll
            for (int j = 0; j < 4; j++)
#pragma unroll
                for (int v = 0; v < 4; v++) acc[i][j][v] = 0.f;

#pragma unroll
        for (int ks = 0; ks < 2; ks++) {
            uint32_t bfr[2][4];
#pragma unroll
            for (int ig = 0; ig < 2; ig++) {
                int row = brow + ig * 16;
                int c16 = ks * 2 + bc16;
                uint32_t off = (uint32_t)row * 64u + (uint32_t)((c16 ^ ((row & 6) >> 1)) * 16);
                ldsm4(bfr[ig], kb + off);
            }
#pragma unroll
            for (int im = 0; im < 4; im++)
#pragma unroll
                for (int ig = 0; ig < 2; ig++) {
                    mma16816_f16(acc[im][ig * 2 + 0], afr[im][ks], &bfr[ig][0]);
                    mma16816_f16(acc[im][ig * 2 + 1], afr[im][ks], &bfr[ig][2]);
                }
        }
        __syncthreads();

        const int j0 = jt * 128;
#pragma unroll
        for (int im = 0; im < 4; im++) {
            const size_t rbase0 = (size_t)(rl0 + im * 16) * LL + j0;
            const size_t rbase1 = rbase0 + (size_t)8 * LL;
            float s0 = 0.f, s1 = 0.f;
#pragma unroll
            for (int jn = 0; jn < 4; jn++) {
                float e0 = __expf(acc[im][jn][0]);
                float e1 = __expf(acc[im][jn][1]);
                float e2 = __expf(acc[im][jn][2]);
                float e3 = __expf(acc[im][jn][3]);
                int cc = cc0 + jn * 8;
                __nv_bfloat162 h01 = __floats2bfloat162_rn(e0, e1);
                __nv_bfloat162 h23 = __floats2bfloat162_rn(e2, e3);
                *(__nv_bfloat162*)&Ebase[rbase0 + cc] = h01;
                *(__nv_bfloat162*)&Ebase[rbase1 + cc] = h23;
                s0 += e0 + e1;
                s1 += e2 + e3;
            }
            rsum[im * 2 + 0] += s0;
            rsum[im * 2 + 1] += s1;
        }
    }

#pragma unroll
    for (int off = 1; off <= 2; off <<= 1)
#pragma unroll
        for (int r = 0; r < 8; r++)
            rsum[r] += __shfl_xor_sync(0xffffffffu, rsum[r], off);

    if ((l & 3) == 0) {
#pragma unroll
        for (int im = 0; im < 4; im++) {
            srs[wn][rl0 + im * 16]     = rsum[im * 2 + 0];
            srs[wn][rl0 + im * 16 + 8] = rsum[im * 2 + 1];
        }
    }
    __syncthreads();
    if (t < 128) {
        g_rowsum[b * LL + i0 + t] = srs[0][t] + srs[1][t] + srs[2][t] + srs[3][t];
    }
}

// ---------------- kernel 4: out = gamma * (v @ E^T)/rowsum + x --------------
// mma.sync bf16 NT GEMM: D[128c x 256i] per CTA, K = 4096, KT = 32,
// double-buffered cp.async, 8 warps of 64x64, 128 fp32 accumulators/thread.
#define KT      32
#define TILEA   (128 * KT * 2)   // 8192 bytes A tile
#define TILEBB  (256 * KT * 2)   // 16384 bytes B tile

__global__ __launch_bounds__(256, 1) void pv_kernel(const float* __restrict__ x,
                                                    const float* __restrict__ gamma,
                                                    float* __restrict__ out) {
    __shared__ __align__(1024) uint8_t sA[2][TILEA];
    __shared__ __align__(1024) uint8_t sB[2][TILEBB];

    const int b  = blockIdx.z;
    const int n0 = blockIdx.x * 256;   // i (output col / E row)
    const int m0 = blockIdx.y * 128;   // c (output row / V row)

    const int t   = threadIdx.x;
    const int w   = t >> 5;
    const int l   = t & 31;
    const int wm  = w & 1;    // 0..1 : 64-row block
    const int wn  = w >> 1;   // 0..3 : 64-col block

    const uint32_t sAa = smem_u32(sA);
    const uint32_t sBa = smem_u32(sB);

    // loaders: thread t loads 64B-row chunks; 4 threads per row
    const int ldr = t >> 2;
    const int ldc = t & 3;
    const __nv_bfloat16* Ag = g_vh + ((size_t)b * CC + m0 + ldr) * LL + ldc * 8;
    const __nv_bfloat16* Bg = g_Eh + ((size_t)b * LL + n0 + ldr) * LL + ldc * 8;
    const uint32_t a_off0 = sw64((uint32_t)ldr * 64u + (uint32_t)ldc * 16u);
    const uint32_t a_off1 = sw64((uint32_t)(ldr + 64) * 64u + (uint32_t)ldc * 16u);
    uint32_t b_off[4];
#pragma unroll
    for (int r = 0; r < 4; r++)
        b_off[r] = sw64((uint32_t)(ldr + 64 * r) * 64u + (uint32_t)ldc * 16u);

    float acc[4][8][4];
#pragma unroll
    for (int i = 0; i < 4; i++)
#pragma unroll
        for (int j = 0; j < 8; j++)
#pragma unroll
            for (int v = 0; v < 4; v++) acc[i][j][v] = 0.f;

    const int NKT = LL / KT;   // 128

    // prefetch tile 0 into buffer 0
    {
        cp_async16(sAa + a_off0, Ag);
        cp_async16(sAa + a_off1, Ag + (size_t)64 * LL);
#pragma unroll
        for (int r = 0; r < 4; r++)
            cp_async16(sBa + b_off[r], Bg + (size_t)(64 * r) * LL);
        CP_COMMIT();
    }

    // ldmatrix per-lane base indices
    const int arow = wm * 64 + (l & 15);
    const int ac16 = (l >> 4);
    const int brow = wn * 64 + (l & 7) + ((l >> 4) << 3);
    const int bc16 = ((l >> 3) & 1);

    for (int kt = 0; kt < NKT; kt++) {
        const int buf = kt & 1;

        if (kt + 1 < NKT) {
            const __nv_bfloat16* Ag2 = Ag + (size_t)(kt + 1) * KT;
            const __nv_bfloat16* Bg2 = Bg + (size_t)(kt + 1) * KT;
            const uint32_t da = sAa + (buf ^ 1) * TILEA;
            const uint32_t db = sBa + (buf ^ 1) * TILEBB;
            cp_async16(da + a_off0, Ag2);
            cp_async16(da + a_off1, Ag2 + (size_t)64 * LL);
#pragma unroll
            for (int r = 0; r < 4; r++)
                cp_async16(db + b_off[r], Bg2 + (size_t)(64 * r) * LL);
            CP_COMMIT();
            CP_WAIT(1);
        } else {
            CP_WAIT(0);
        }
        __syncthreads();

        const uint32_t abase = sAa + buf * TILEA;
        const uint32_t bbase = sBa + buf * TILEBB;

#pragma unroll
        for (int ks = 0; ks < 2; ks++) {
            uint32_t afr[4][4];
#pragma unroll
            for (int im = 0; im < 4; im++) {
                int row = arow + im * 16;
                int c16 = ks * 2 + ac16;
                uint32_t off = (uint32_t)row * 64u + (uint32_t)((c16 ^ ((row & 6) >> 1)) * 16);
                ldsm4(afr[im], abase + off);
            }
            uint32_t bfr[4][4];
#pragma unroll
            for (int ig = 0; ig < 4; ig++) {
                int row = brow + ig * 16;
                int c16 = ks * 2 + bc16;
                uint32_t off = (uint32_t)row * 64u + (uint32_t)((c16 ^ ((row & 6) >> 1)) * 16);
                ldsm4(bfr[ig], bbase + off);
            }
#pragma unroll
            for (int im = 0; im < 4; im++) {
#pragma unroll
                for (int ig = 0; ig < 4; ig++) {
                    mma16816_bf16(acc[im][ig * 2 + 0], afr[im], &bfr[ig][0]);
                    mma16816_bf16(acc[im][ig * 2 + 1], afr[im], &bfr[ig][2]);
                }
            }
        }
        __syncthreads();
    }

    // ---- epilogue: normalize by rowsum, scale by gamma, add residual x ----
    float* sInv = (float*)sA;
    sInv[t] = 1.0f / g_rowsum[b * LL + n0 + t];
    __syncthreads();

    const float g = *gamma;

#pragma unroll
    for (int im = 0; im < 4; im++) {
        int r0 = m0 + wm * 64 + im * 16 + (l >> 2);
#pragma unroll
        for (int jn = 0; jn < 8; jn++) {
            int cc = wn * 64 + jn * 8 + 2 * (l & 3);
            float2 inv = *(float2*)&sInv[cc];

            size_t base0 = ((size_t)b * CC + r0) * LL + n0 + cc;
            float2 xv0 = *(const float2*)&x[base0];
            float2 o0;
            o0.x = g * acc[im][jn][0] * inv.x + xv0.x;
            o0.y = g * acc[im][jn][1] * inv.y + xv0.y;
            *(float2*)&out[base0] = o0;

            size_t base1 = base0 + (size_t)8 * LL;
            float2 xv1 = *(const float2*)&x[base1];
            float2 o1;
            o1.x = g * acc[im][jn][2] * inv.x + xv1.x;
            o1.y = g * acc[im][jn][3] * inv.y + xv1.y;
            *(float2*)&out[base1] = o1;
        }
    }
}

// ---------------- launch ----------------------------------------------------
extern "C" void kernel_launch(void* const* d_in, const int* in_sizes, int n_in,
                              void* d_out, int out_size) {
    const float* x     = (const float*)d_in[0];
    const float* Wq    = (const float*)d_in[1];
    const float* bq    = (const float*)d_in[2];
    const float* Wk    = (const float*)d_in[3];
    const float* bk    = (const float*)d_in[4];
    const float* Wv    = (const float*)d_in[5];
    const float* bv    = (const float*)d_in[6];
    const float* gamma = (const float*)d_in[7];
    float* out = (float*)d_out;

    pack_kernel<<<320, 256>>>(Wq, bq, Wk, bk, Wv, bv);
    qkv_kernel<<<dim3(LL / 64, OTOT / 64, BB), 256>>>(x);
    attn_mma_kernel<<<dim3(LL / 128, BB), 256>>>();
    pv_kernel<<<dim3(LL / 256, CC / 128, BB), 256>>>(x, gamma, out);
}

// round 12
// speedup vs baseline: 1.3402x; 1.3402x over previous
#include <cuda_runtime.h>
#include <cuda_bf16.h>
#include <cuda_fp16.h>
#include <cstdint>
#include <cstddef>

#define BB   4
#define CC   256
#define LL   4096
#define C8   32
#define OTOT 320   // 32 q + 32 k + 256 v rows

// ---------------- scratch (device globals; no allocation allowed) ----------
__device__ float g_bias[OTOT];
__device__ __align__(256) __half g_Wh[OTOT * CC];                     // packed [Wq;Wk;Wv] fp16
__device__ __align__(256) __half g_xh[(size_t)BB * LL * CC];          // x transposed fp16 [b][l][c]
__device__ __align__(256) __nv_bfloat16 g_vh[(size_t)BB * CC * LL];   // v in bf16
__device__ __align__(256) __half g_qT[(size_t)BB * LL * C8];          // q transposed fp16 [b][i][c]
__device__ __align__(256) __half g_kT[(size_t)BB * LL * C8];          // k transposed fp16 [b][j][c]
__device__ __align__(256) __nv_bfloat16 g_Eh[(size_t)BB * LL * LL];   // exp(S) bf16 (128 MB)
__device__ float g_rowsum[BB * LL];

// ---------------- PTX helpers (sm_80-era only: family-target safe) ----------
__device__ __forceinline__ uint32_t smem_u32(const void* p) {
    uint32_t a;
    asm("{ .reg .u64 t; cvta.to.shared.u64 t, %1; cvt.u32.u64 %0, t; }" : "=r"(a) : "l"(p));
    return a;
}
__device__ __forceinline__ void cp_async16(uint32_t dst, const void* src) {
    asm volatile("cp.async.cg.shared.global [%0], [%1], 16;" :: "r"(dst), "l"(src));
}
#define CP_COMMIT() asm volatile("cp.async.commit_group;" ::: "memory")
#define CP_WAIT(n)  asm volatile("cp.async.wait_group %0;" :: "n"(n) : "memory")

__device__ __forceinline__ void ldsm4(uint32_t* r, uint32_t addr) {
    asm volatile("ldmatrix.sync.aligned.m8n8.x4.shared.b16 {%0,%1,%2,%3}, [%4];"
                 : "=r"(r[0]), "=r"(r[1]), "=r"(r[2]), "=r"(r[3]) : "r"(addr));
}
__device__ __forceinline__ void mma16816_bf16(float* d, const uint32_t* a, const uint32_t* b) {
    asm volatile(
        "mma.sync.aligned.m16n8k16.row.col.f32.bf16.bf16.f32 "
        "{%0,%1,%2,%3}, {%4,%5,%6,%7}, {%8,%9}, {%0,%1,%2,%3};"
        : "+f"(d[0]), "+f"(d[1]), "+f"(d[2]), "+f"(d[3])
        : "r"(a[0]), "r"(a[1]), "r"(a[2]), "r"(a[3]), "r"(b[0]), "r"(b[1]));
}
__device__ __forceinline__ void mma16816_f16(float* d, const uint32_t* a, const uint32_t* b) {
    asm volatile(
        "mma.sync.aligned.m16n8k16.row.col.f32.f16.f16.f32 "
        "{%0,%1,%2,%3}, {%4,%5,%6,%7}, {%8,%9}, {%0,%1,%2,%3};"
        : "+f"(d[0]), "+f"(d[1]), "+f"(d[2]), "+f"(d[3])
        : "r"(a[0]), "r"(a[1]), "r"(a[2]), "r"(a[3]), "r"(b[0]), "r"(b[1]));
}

// SW64 swizzle for 64-byte rows.
__device__ __forceinline__ uint32_t sw64(uint32_t off) {
    return off ^ ((off >> 3) & 0x30);
}

// ---------------- kernel 0: pack weights (fp16) + biases --------------------
__global__ void pack_kernel(const float* __restrict__ Wq, const float* __restrict__ bq,
                            const float* __restrict__ Wk, const float* __restrict__ bk,
                            const float* __restrict__ Wv, const float* __restrict__ bv) {
    int tid = blockIdx.x * blockDim.x + threadIdx.x;
    int stride = gridDim.x * blockDim.x;
    for (int idx = tid; idx < OTOT * CC; idx += stride) {
        int o = idx / CC;
        int c = idx % CC;
        float w;
        if (o < 32)       w = Wq[o * CC + c];
        else if (o < 64)  w = Wk[(o - 32) * CC + c];
        else              w = Wv[(o - 64) * CC + c];
        g_Wh[idx] = __float2half(w);
    }
    if (tid < OTOT) {
        g_bias[tid] = (tid < 32) ? bq[tid] : (tid < 64) ? bk[tid - 32] : bv[tid - 64];
    }
}

// ---------------- kernel 0b: xT = transpose(x) in fp16 ----------------------
// x [b][c][l] fp32 -> g_xh [b][l][c] fp16. 64x64 tiles.
__global__ __launch_bounds__(256) void xt_kernel(const float* __restrict__ x) {
    __shared__ float s[64][65];
    const int b  = blockIdx.z;
    const int c0 = blockIdx.y * 64;
    const int l0 = blockIdx.x * 64;
    const int t  = threadIdx.x;

    for (int i = t; i < 64 * 64; i += 256) {
        int r  = i >> 6;
        int cl = i & 63;
        s[r][cl] = x[((size_t)b * CC + c0 + r) * LL + l0 + cl];
    }
    __syncthreads();
    for (int i = t; i < 64 * 32; i += 256) {
        int r2 = i >> 5;          // l within tile
        int c2 = (i & 31) * 2;    // c pair within tile
        __half2 h = __floats2half2_rn(s[c2][r2], s[c2 + 1][r2]);
        *(__half2*)&g_xh[((size_t)b * LL + l0 + r2) * CC + c0 + c2] = h;
    }
}

// ---------------- kernel 1: qkvT[o][l] = W[o][c] . xT[l][c] via mma ---------
// CTA: 64 o-rows x 256 l-cols, K = 256 (KT=32, double buffered).
// 8 warps, each 64(o) x 32(l). o-tile 0 -> q/k (fp16 scatter); 1..4 -> v bf16.
__global__ __launch_bounds__(256) void qkvT_kernel() {
    __shared__ __align__(1024) uint8_t sW[2][4096];
    __shared__ __align__(1024) uint8_t sX[2][16384];
    __shared__ float sBias[64];

    const int b  = blockIdx.z;
    const int oy = blockIdx.y;          // 0..4
    const int o0 = oy * 64;
    const int l0 = blockIdx.x * 256;

    const int t  = threadIdx.x;
    const int w  = t >> 5;
    const int l  = t & 31;
    const int wn = w;                   // n-block (32 l each)

    const uint32_t sWa = smem_u32(sW);
    const uint32_t sXa = smem_u32(sX);

    // loaders
    const int ra = t >> 2;      // 0..63
    const int ca = t & 3;       // 16B chunk
    const __half* Wg = g_Wh + (o0 + ra) * CC + ca * 8;
    const __half* Xg = g_xh + ((size_t)b * LL + l0 + ra) * CC + ca * 8;
    const uint32_t aoff = sw64((uint32_t)ra * 64u + (uint32_t)ca * 16u);
    uint32_t xoff[4];
#pragma unroll
    for (int r = 0; r < 4; r++)
        xoff[r] = sw64((uint32_t)(ra + 64 * r) * 64u + (uint32_t)ca * 16u);

    if (t < 64) sBias[t] = g_bias[o0 + t];

    // prefetch kt=0 into buf 0
    cp_async16(sWa + aoff, Wg);
#pragma unroll
    for (int r = 0; r < 4; r++)
        cp_async16(sXa + xoff[r], Xg + (size_t)(64 * r) * CC);
    CP_COMMIT();

    float acc[4][4][4];
#pragma unroll
    for (int i = 0; i < 4; i++)
#pragma unroll
        for (int j = 0; j < 4; j++)
#pragma unroll
            for (int v = 0; v < 4; v++) acc[i][j][v] = 0.f;

    const int arow = (l & 15);
    const int ac16 = l >> 4;
    const int brow = wn * 32 + (l & 7) + ((l >> 4) << 3);
    const int bc16 = (l >> 3) & 1;

    const int NKQ = CC / 32;   // 8
    for (int kt = 0; kt < NKQ; kt++) {
        const int buf = kt & 1;
        if (kt + 1 < NKQ) {
            const uint32_t dw = sWa + (buf ^ 1) * 4096;
            const uint32_t dx = sXa + (buf ^ 1) * 16384;
            cp_async16(dw + aoff, Wg + (kt + 1) * 32);
#pragma unroll
            for (int r = 0; r < 4; r++)
                cp_async16(dx + xoff[r], Xg + (size_t)(64 * r) * CC + (kt + 1) * 32);
            CP_COMMIT();
            CP_WAIT(1);
        } else {
            CP_WAIT(0);
        }
        __syncthreads();

        const uint32_t ab = sWa + buf * 4096;
        const uint32_t bb = sXa + buf * 16384;
#pragma unroll
        for (int ks = 0; ks < 2; ks++) {
            uint32_t afr[4][4];
#pragma unroll
            for (int im = 0; im < 4; im++) {
                int row = arow + im * 16;
                int c16 = ks * 2 + ac16;
                uint32_t off = (uint32_t)row * 64u + (uint32_t)((c16 ^ ((row & 6) >> 1)) * 16);
                ldsm4(afr[im], ab + off);
            }
            uint32_t bfr[2][4];
#pragma unroll
            for (int ig = 0; ig < 2; ig++) {
                int row = brow + ig * 16;
                int c16 = ks * 2 + bc16;
                uint32_t off = (uint32_t)row * 64u + (uint32_t)((c16 ^ ((row & 6) >> 1)) * 16);
                ldsm4(bfr[ig], bb + off);
            }
#pragma unroll
            for (int im = 0; im < 4; im++)
#pragma unroll
                for (int ig = 0; ig < 2; ig++) {
                    mma16816_f16(acc[im][ig * 2 + 0], afr[im], &bfr[ig][0]);
                    mma16816_f16(acc[im][ig * 2 + 1], afr[im], &bfr[ig][2]);
                }
        }
        __syncthreads();
    }

    // ---- epilogue ----
    const int lr  = l >> 2;
    const int lc2 = 2 * (l & 3);

#pragma unroll
    for (int im = 0; im < 4; im++) {
        const int or0 = im * 16 + lr;    // local o row for d0,d1
        const int or1 = or0 + 8;         // local o row for d2,d3
        const float b0 = sBias[or0];
        const float b1 = sBias[or1];
#pragma unroll
        for (int jn = 0; jn < 4; jn++) {
            const int lc = wn * 32 + jn * 8 + lc2;
            float v00 = acc[im][jn][0] + b0, v01 = acc[im][jn][1] + b0;
            float v10 = acc[im][jn][2] + b1, v11 = acc[im][jn][3] + b1;

            if (oy == 0) {
                const size_t lidx = (size_t)b * LL + l0 + lc;
                if (im < 2) {   // o in 0..31 : q
                    g_qT[lidx * C8 + or0]       = __float2half(v00);
                    g_qT[(lidx + 1) * C8 + or0] = __float2half(v01);
                    g_qT[lidx * C8 + or1]       = __float2half(v10);
                    g_qT[(lidx + 1) * C8 + or1] = __float2half(v11);
                } else {        // o in 32..63 : k
                    g_kT[lidx * C8 + or0 - 32]       = __float2half(v00);
                    g_kT[(lidx + 1) * C8 + or0 - 32] = __float2half(v01);
                    g_kT[lidx * C8 + or1 - 32]       = __float2half(v10);
                    g_kT[(lidx + 1) * C8 + or1 - 32] = __float2half(v11);
                }
            } else {
                const int vr0 = (oy - 1) * 64 + or0;
                const int vr1 = vr0 + 8;
                *(__nv_bfloat162*)&g_vh[((size_t)b * CC + vr0) * LL + l0 + lc] =
                    __floats2bfloat162_rn(v00, v01);
                *(__nv_bfloat162*)&g_vh[((size_t)b * CC + vr1) * LL + l0 + lc] =
                    __floats2bfloat162_rn(v10, v11);
            }
        }
    }
}

// ---------------- kernel 2: E = exp(q^T k) via mma.sync fp16 ---------------
#define NJ   (LL / 128)      // 32
#define KTB  (128 * 64)      // 8192 bytes per k tile (128 rows x 32 fp16)

__global__ __launch_bounds__(256) void attn_mma_kernel() {
    __shared__ __align__(1024) uint8_t sQ[KTB];
    __shared__ __align__(1024) uint8_t sK[2][KTB];
    __shared__ float srs[4][128];

    const int b  = blockIdx.y;
    const int i0 = blockIdx.x * 128;

    const int t = threadIdx.x;
    const int w = t >> 5;
    const int l = t & 31;
    const int wm = w & 1;
    const int wn = w >> 1;

    const uint32_t sQa = smem_u32(sQ);
    const uint32_t sKa = smem_u32(sK);

    const int ldr = t >> 1;
    const int ldc = (t & 1) * 2;
    const uint32_t off0 = sw64((uint32_t)ldr * 64u + (uint32_t)ldc * 16u);
    const uint32_t off1 = sw64((uint32_t)ldr * 64u + (uint32_t)ldc * 16u + 16u);

    const __half* Qg = g_qT + ((size_t)b * LL + i0 + ldr) * C8 + ldc * 8;
    cp_async16(sQa + off0, Qg);
    cp_async16(sQa + off1, Qg + 8);
    CP_COMMIT();
    {
        const __half* Kg = g_kT + ((size_t)b * LL + ldr) * C8 + ldc * 8;
        cp_async16(sKa + off0, Kg);
        cp_async16(sKa + off1, Kg + 8);
        CP_COMMIT();
    }

    CP_WAIT(1);
    __syncthreads();

    const int arow = wm * 64 + (l & 15);
    const int ac16 = l >> 4;
    uint32_t afr[4][2][4];
#pragma unroll
    for (int im = 0; im < 4; im++)
#pragma unroll
        for (int ks = 0; ks < 2; ks++) {
            int row = arow + im * 16;
            int c16 = ks * 2 + ac16;
            uint32_t off = (uint32_t)row * 64u + (uint32_t)((c16 ^ ((row & 6) >> 1)) * 16);
            ldsm4(afr[im][ks], sQa + off);
        }

    const int brow = wn * 32 + (l & 7) + ((l >> 4) << 3);
    const int bc16 = (l >> 3) & 1;

    float rsum[8];
#pragma unroll
    for (int r = 0; r < 8; r++) rsum[r] = 0.f;

    __nv_bfloat16* Ebase = g_Eh + ((size_t)b * LL + i0) * LL;

    const int rl0 = wm * 64 + (l >> 2);
    const int cc0 = wn * 32 + 2 * (l & 3);

#pragma unroll 1
    for (int jt = 0; jt < NJ; jt++) {
        const int buf = jt & 1;

        if (jt + 1 < NJ) {
            const __half* Kg2 = g_kT + ((size_t)b * LL + (jt + 1) * 128 + ldr) * C8 + ldc * 8;
            uint32_t d = sKa + (buf ^ 1) * KTB;
            cp_async16(d + off0, Kg2);
            cp_async16(d + off1, Kg2 + 8);
            CP_COMMIT();
            CP_WAIT(1);
        } else {
            CP_WAIT(0);
        }
        __syncthreads();

        const uint32_t kb = sKa + buf * KTB;

        float acc[4][4][4];
#pragma unroll
        for (int i = 0; i < 4; i++)
#pragma unroll
            for (int j = 0; j < 4; j++)
#pragma unroll
                for (int v = 0; v < 4; v++) acc[i][j][v] = 0.f;

#pragma unroll
        for (int ks = 0; ks < 2; ks++) {
            uint32_t bfr[2][4];
#pragma unroll
            for (int ig = 0; ig < 2; ig++) {
                int row = brow + ig * 16;
                int c16 = ks * 2 + bc16;
                uint32_t off = (uint32_t)row * 64u + (uint32_t)((c16 ^ ((row & 6) >> 1)) * 16);
                ldsm4(bfr[ig], kb + off);
            }
#pragma unroll
            for (int im = 0; im < 4; im++)
#pragma unroll
                for (int ig = 0; ig < 2; ig++) {
                    mma16816_f16(acc[im][ig * 2 + 0], afr[im][ks], &bfr[ig][0]);
                    mma16816_f16(acc[im][ig * 2 + 1], afr[im][ks], &bfr[ig][2]);
                }
        }
        __syncthreads();

        const int j0 = jt * 128;
#pragma unroll
        for (int im = 0; im < 4; im++) {
            const size_t rbase0 = (size_t)(rl0 + im * 16) * LL + j0;
            const size_t rbase1 = rbase0 + (size_t)8 * LL;
            float s0 = 0.f, s1 = 0.f;
#pragma unroll
            for (int jn = 0; jn < 4; jn++) {
                float e0 = __expf(acc[im][jn][0]);
                float e1 = __expf(acc[im][jn][1]);
                float e2 = __expf(acc[im][jn][2]);
                float e3 = __expf(acc[im][jn][3]);
                int cc = cc0 + jn * 8;
                __nv_bfloat162 h01 = __floats2bfloat162_rn(e0, e1);
                __nv_bfloat162 h23 = __floats2bfloat162_rn(e2, e3);
                *(__nv_bfloat162*)&Ebase[rbase0 + cc] = h01;
                *(__nv_bfloat162*)&Ebase[rbase1 + cc] = h23;
                s0 += e0 + e1;
                s1 += e2 + e3;
            }
            rsum[im * 2 + 0] += s0;
            rsum[im * 2 + 1] += s1;
        }
    }

#pragma unroll
    for (int off = 1; off <= 2; off <<= 1)
#pragma unroll
        for (int r = 0; r < 8; r++)
            rsum[r] += __shfl_xor_sync(0xffffffffu, rsum[r], off);

    if ((l & 3) == 0) {
#pragma unroll
        for (int im = 0; im < 4; im++) {
            srs[wn][rl0 + im * 16]     = rsum[im * 2 + 0];
            srs[wn][rl0 + im * 16 + 8] = rsum[im * 2 + 1];
        }
    }
    __syncthreads();
    if (t < 128) {
        g_rowsum[b * LL + i0 + t] = srs[0][t] + srs[1][t] + srs[2][t] + srs[3][t];
    }
}

// ---------------- kernel 4: out = gamma * (v @ E^T)/rowsum + x --------------
// mma.sync bf16 NT GEMM: D[128c x 128i] per CTA, K = 4096, KT = 32,
// 3-stage cp.async pipeline (ONE barrier per k-iter), 8 warps of 64x32.
#define KT      32
#define TILEB   (128 * KT * 2)   // 8192 bytes per operand tile

__global__ __launch_bounds__(256, 2) void pv_kernel(const float* __restrict__ x,
                                                    const float* __restrict__ gamma,
                                                    float* __restrict__ out) {
    __shared__ __align__(1024) uint8_t sA[3][TILEB];
    __shared__ __align__(1024) uint8_t sB[3][TILEB];

    const int b  = blockIdx.z;
    const int n0 = blockIdx.x * 128;   // i (output col / E row)
    const int m0 = blockIdx.y * 128;   // c (output row / V row)

    const int t   = threadIdx.x;
    const int w   = t >> 5;
    const int l   = t & 31;
    const int wm  = w & 1;
    const int wn  = w >> 1;

    const uint32_t sAa = smem_u32(sA);
    const uint32_t sBa = smem_u32(sB);

    const int ldr = t >> 2;
    const int ldc = t & 3;
    const __nv_bfloat16* Ag = g_vh + ((size_t)b * CC + m0 + ldr) * LL + ldc * 8;
    const __nv_bfloat16* Bg = g_Eh + ((size_t)b * LL + n0 + ldr) * LL + ldc * 8;
    const uint32_t dst_off0 = sw64((uint32_t)ldr * 64u + (uint32_t)ldc * 16u);
    const uint32_t dst_off1 = sw64((uint32_t)(ldr + 64) * 64u + (uint32_t)ldc * 16u);

    float acc[4][4][4];
#pragma unroll
    for (int i = 0; i < 4; i++)
#pragma unroll
        for (int j = 0; j < 4; j++)
#pragma unroll
            for (int v = 0; v < 4; v++) acc[i][j][v] = 0.f;

    const int NKT = LL / KT;   // 128

    // prefetch tiles 0,1 into buffers 0,1
#pragma unroll
    for (int s = 0; s < 2; s++) {
        const uint32_t da = sAa + s * TILEB;
        const uint32_t db = sBa + s * TILEB;
        cp_async16(da + dst_off0, Ag + (size_t)s * KT);
        cp_async16(da + dst_off1, Ag + (size_t)s * KT + (size_t)64 * LL);
        cp_async16(db + dst_off0, Bg + (size_t)s * KT);
        cp_async16(db + dst_off1, Bg + (size_t)s * KT + (size_t)64 * LL);
        CP_COMMIT();
    }

    const int arow = wm * 64 + (l & 15);
    const int ac16 = (l >> 4);
    const int brow = wn * 32 + (l & 7) + ((l >> 4) << 3);
    const int bc16 = ((l >> 3) & 1);

    for (int kt = 0; kt < NKT; kt++) {
        const int buf = kt % 3;

        // tile kt resident? (outstanding groups: kt+1 [, kt+2 not yet issued])
        if (kt + 1 < NKT) { CP_WAIT(1); } else { CP_WAIT(0); }
        __syncthreads();   // also: all warps done computing tile kt-1

        // prefetch tile kt+2 into buffer (kt+2)%3 == (kt-1)%3 (free now)
        if (kt + 2 < NKT) {
            const int pbuf = (kt + 2) % 3;
            const __nv_bfloat16* Ag2 = Ag + (size_t)(kt + 2) * KT;
            const __nv_bfloat16* Bg2 = Bg + (size_t)(kt + 2) * KT;
            const uint32_t da = sAa + pbuf * TILEB;
            const uint32_t db = sBa + pbuf * TILEB;
            cp_async16(da + dst_off0, Ag2);
            cp_async16(da + dst_off1, Ag2 + (size_t)64 * LL);
            cp_async16(db + dst_off0, Bg2);
            cp_async16(db + dst_off1, Bg2 + (size_t)64 * LL);
            CP_COMMIT();
        }

        const uint32_t abase = sAa + buf * TILEB;
        const uint32_t bbase = sBa + buf * TILEB;

#pragma unroll
        for (int ks = 0; ks < 2; ks++) {
            uint32_t afr[4][4];
#pragma unroll
            for (int im = 0; im < 4; im++) {
                int row = arow + im * 16;
                int c16 = ks * 2 + ac16;
                uint32_t off = (uint32_t)row * 64u + (uint32_t)((c16 ^ ((row & 6) >> 1)) * 16);
                ldsm4(afr[im], abase + off);
            }
            uint32_t bfr[2][4];
#pragma unroll
            for (int ig = 0; ig < 2; ig++) {
                int row = brow + ig * 16;
                int c16 = ks * 2 + bc16;
                uint32_t off = (uint32_t)row * 64u + (uint32_t)((c16 ^ ((row & 6) >> 1)) * 16);
                ldsm4(bfr[ig], bbase + off);
            }
#pragma unroll
            for (int im = 0; im < 4; im++) {
#pragma unroll
                for (int ig = 0; ig < 2; ig++) {
                    mma16816_bf16(acc[im][ig * 2 + 0], afr[im], &bfr[ig][0]);
                    mma16816_bf16(acc[im][ig * 2 + 1], afr[im], &bfr[ig][2]);
                }
            }
        }
        // no trailing barrier: next iter's top barrier protects buffer reuse
    }

    // ---- epilogue: normalize by rowsum, scale by gamma, add residual x ----
    // sInv lives in sA[0] region: disjoint from buf 1 (tile 127) still being read.
    float* sInv = (float*)sA;
    if (t < 128) sInv[t] = 1.0f / g_rowsum[b * LL + n0 + t];
    __syncthreads();

    const float g = *gamma;

#pragma unroll
    for (int im = 0; im < 4; im++) {
        int r0 = m0 + wm * 64 + im * 16 + (l >> 2);
#pragma unroll
        for (int jn = 0; jn < 4; jn++) {
            int cc = wn * 32 + jn * 8 + 2 * (l & 3);
            float2 inv = *(float2*)&sInv[cc];

            size_t base0 = ((size_t)b * CC + r0) * LL + n0 + cc;
            float2 xv0 = *(const float2*)&x[base0];
            float2 o0;
            o0.x = g * acc[im][jn][0] * inv.x + xv0.x;
            o0.y = g * acc[im][jn][1] * inv.y + xv0.y;
            *(float2*)&out[base0] = o0;

            size_t base1 = base0 + (size_t)8 * LL;
            float2 xv1 = *(const float2*)&x[base1];
            float2 o1;
            o1.x = g * acc[im][jn][2] * inv.x + xv1.x;
            o1.y = g * acc[im][jn][3] * inv.y + xv1.y;
            *(float2*)&out[base1] = o1;
        }
    }
}

// ---------------- launch ----------------------------------------------------
extern "C" void kernel_launch(void* const* d_in, const int* in_sizes, int n_in,
                              void* d_out, int out_size) {
    const float* x     = (const float*)d_in[0];
    const float* Wq    = (const float*)d_in[1];
    const float* bq    = (const float*)d_in[2];
    const float* Wk    = (const float*)d_in[3];
    const float* bk    = (const float*)d_in[4];
    const float* Wv    = (const float*)d_in[5];
    const float* bv    = (const float*)d_in[6];
    const float* gamma = (const float*)d_in[7];
    float* out = (float*)d_out;

    pack_kernel<<<320, 256>>>(Wq, bq, Wk, bk, Wv, bv);
    xt_kernel<<<dim3(LL / 64, CC / 64, BB), 256>>>(x);
    qkvT_kernel<<<dim3(LL / 256, OTOT / 64, BB), 256>>>();
    attn_mma_kernel<<<dim3(LL / 128, BB), 256>>>();
    pv_kernel<<<dim3(LL / 128, CC / 128, BB), 256>>>(x, gamma, out);
}